// round 2
// baseline (speedup 1.0000x reference)
#include <cuda_runtime.h>

// GCN link predictor, restructured:
//   y1 = x @ w1                      (dense GEMM, chunked 32 cols at a time)
//   h1 = b1 + A_scatter(y1)          (SpMM, vec4 red.global, per chunk)
//   y2 = relu(h1) @ w2               (dense GEMM, relu fused on load, chunked)
//   out = b2 + A_scatter(y2)         (SpMM per chunk)
// Valid because relu((A@x)@w1+b1) == relu(A@(x@w1)+b1) and
// (A@h1)@w2+b2 == A@(h1@w2)+b2: halves channel volume of the second SpMM.
//
// Scratch kept to 64MB (tight free-memory budget in the bench container):
//   g_h1  : N x 128 fp32 accumulator (51.2MB)
//   g_tmp : N x 32  fp32 chunk buffer (12.8MB), reused 6x

#define MAX_NODES 100000

__device__ float g_h1[(size_t)MAX_NODES * 128];
__device__ float g_tmp[(size_t)MAX_NODES * 32];

// ---------------------------------------------------------------------------
// init: out[n*C + c] = bias[c]   (C power of two; cmask = C-1)
// ---------------------------------------------------------------------------
__global__ void init_bias_kernel(float* __restrict__ out,
                                 const float* __restrict__ bias,
                                 int total, int cmask) {
    int i = blockIdx.x * blockDim.x + threadIdx.x;
    if (i < total) out[i] = bias[i & cmask];
}

// ---------------------------------------------------------------------------
// GEMM chunk: C[N, 32] = act(A)[N, 128] @ W[128, c0:c0+32]
// W is row-major [128, WN]. BM=64, BK=32, 256 threads, 8 outputs/thread.
// A tile staged transposed in smem.
// ---------------------------------------------------------------------------
template <bool RELU>
__global__ __launch_bounds__(256) void gemm_chunk32_kernel(
    const float* __restrict__ A, const float* __restrict__ W,
    float* __restrict__ C, int N, int WN, int c0) {
    constexpr int BM = 64, BK = 32, K = 128, BN = 32;

    __shared__ float As[BK][BM];      // transposed A tile
    __shared__ float Ws[BK][BN];

    const int tid = threadIdx.x;
    const int m0  = blockIdx.x * BM;
    const int tx  = tid & 31;         // output column (0..31)
    const int ty  = tid >> 5;         // output row group (0..7)

    float acc[8];
#pragma unroll
    for (int m = 0; m < 8; ++m) acc[m] = 0.f;

    const int ar  = tid >> 3;         // 0..31  (A-tile load row)
    const int ac4 = (tid & 7) * 4;    // 0,4,...,28 (A-tile load col)
    const int wk  = tid >> 3;         // 0..31  (W-tile load row)
    const int wc4 = (tid & 7) * 4;    // 0,4,...,28 (W-tile load col)

    for (int kt = 0; kt < K; kt += BK) {
        // --- load A tile (64 x 32), store transposed ---
#pragma unroll
        for (int i = 0; i < 2; ++i) {
            int row = m0 + ar + i * 32;
            float4 v = make_float4(0.f, 0.f, 0.f, 0.f);
            if (row < N)
                v = *reinterpret_cast<const float4*>(A + (size_t)row * K + kt + ac4);
            if (RELU) {
                v.x = fmaxf(v.x, 0.f); v.y = fmaxf(v.y, 0.f);
                v.z = fmaxf(v.z, 0.f); v.w = fmaxf(v.w, 0.f);
            }
            int r = ar + i * 32;
            As[ac4 + 0][r] = v.x;
            As[ac4 + 1][r] = v.y;
            As[ac4 + 2][r] = v.z;
            As[ac4 + 3][r] = v.w;
        }
        // --- load W tile (32 x 32): one float4 per thread ---
        *reinterpret_cast<float4*>(&Ws[wk][wc4]) =
            *reinterpret_cast<const float4*>(W + (size_t)(kt + wk) * WN + c0 + wc4);
        __syncthreads();

#pragma unroll
        for (int k = 0; k < BK; ++k) {
            float4 a0 = *reinterpret_cast<const float4*>(&As[k][ty * 8]);
            float4 a1 = *reinterpret_cast<const float4*>(&As[k][ty * 8 + 4]);
            float b = Ws[k][tx];
            acc[0] = fmaf(a0.x, b, acc[0]);
            acc[1] = fmaf(a0.y, b, acc[1]);
            acc[2] = fmaf(a0.z, b, acc[2]);
            acc[3] = fmaf(a0.w, b, acc[3]);
            acc[4] = fmaf(a1.x, b, acc[4]);
            acc[5] = fmaf(a1.y, b, acc[5]);
            acc[6] = fmaf(a1.z, b, acc[6]);
            acc[7] = fmaf(a1.w, b, acc[7]);
        }
        __syncthreads();
    }

#pragma unroll
    for (int m = 0; m < 8; ++m) {
        int row = m0 + ty * 8 + m;
        if (row < N) C[(size_t)row * 32 + tx] = acc[m];
    }
}

// ---------------------------------------------------------------------------
// SpMM chunk (32 channels): one 8-lane group per edge.
// Gather tmp[col] (128B contiguous), scale by val, vec4 reduction into
// out[row*LD + c0 + lane*4].
// ---------------------------------------------------------------------------
__global__ __launch_bounds__(256) void spmm_chunk32_kernel(
    const int* __restrict__ row, const int* __restrict__ col,
    const float* __restrict__ val, const float* __restrict__ x,
    float* __restrict__ out, int nE, int LD, int c0) {
    int e    = blockIdx.x * 32 + (threadIdx.x >> 3);
    int lane = threadIdx.x & 7;
    if (e >= nE) return;
    int r = row[e];
    int c = col[e];
    float v = val[e];
    float4 g = *reinterpret_cast<const float4*>(x + (size_t)c * 32 + lane * 4);
    g.x *= v; g.y *= v; g.z *= v; g.w *= v;
    float* dst = out + (size_t)r * LD + c0 + lane * 4;
    asm volatile("red.global.add.v4.f32 [%0], {%1, %2, %3, %4};"
                 :: "l"(dst), "f"(g.x), "f"(g.y), "f"(g.z), "f"(g.w)
                 : "memory");
}

// ---------------------------------------------------------------------------
// launch
// ---------------------------------------------------------------------------
extern "C" void kernel_launch(void* const* d_in, const int* in_sizes, int n_in,
                              void* d_out, int out_size) {
    const float* x   = (const float*)d_in[0];
    const int*   row = (const int*)d_in[1];
    const int*   col = (const int*)d_in[2];
    const float* val = (const float*)d_in[3];
    const float* w1  = (const float*)d_in[4];
    const float* b1  = (const float*)d_in[5];
    const float* w2  = (const float*)d_in[6];
    const float* b2  = (const float*)d_in[7];
    float* out = (float*)d_out;

    const int N = in_sizes[0] >> 7;   // x is [N, 128]
    const int E = in_sizes[1];

    float *h1, *tmp;
    cudaGetSymbolAddress((void**)&h1, g_h1);
    cudaGetSymbolAddress((void**)&tmp, g_tmp);

    const int gemm_blocks = (N + 63) / 64;
    const int spmm_blocks = (E + 31) / 32;

    // h1 = b1 (broadcast over all 128 channels)
    init_bias_kernel<<<(N * 128 + 255) / 256, 256>>>(h1, b1, N * 128, 127);
    // layer 1: 4 chunks of 32 hidden channels
    for (int c0 = 0; c0 < 128; c0 += 32) {
        gemm_chunk32_kernel<false><<<gemm_blocks, 256>>>(x, w1, tmp, N, 128, c0);
        spmm_chunk32_kernel<<<spmm_blocks, 256>>>(row, col, val, tmp, h1, E, 128, c0);
    }
    // out = b2 (broadcast over 64 channels)
    init_bias_kernel<<<(N * 64 + 255) / 256, 256>>>(out, b2, N * 64, 63);
    // layer 2: 2 chunks of 32 output channels (relu fused on h1 load)
    for (int c0 = 0; c0 < 64; c0 += 32) {
        gemm_chunk32_kernel<true><<<gemm_blocks, 256>>>(h1, w2, tmp, N, 64, c0);
        spmm_chunk32_kernel<<<spmm_blocks, 256>>>(row, col, val, tmp, out, E, 64, c0);
    }
}

// round 3
// speedup vs baseline: 1.3620x; 1.3620x over previous
#include <cuda_runtime.h>

// GCN link predictor, restructured + CSR:
//   CSR build (per call): histogram -> scan -> bucket scatter
//   y1 = x @ w1 (chunked 32 cols) ; h1 = b1 + A@y1   (CSR row-gather, no atomics)
//   y2 = relu(h1) @ w2 (chunked)  ; out = b2 + A@y2  (CSR row-gather)
// Valid: relu((A@x)@w1+b1) == relu(A@(x@w1)+b1), (A@h)@w2+b2 == A@(h@w2)+b2.

#define MAX_NODES 100000
#define MAX_EDGES 1600000
#define SCAN_B    1024
#define MAX_BLKS  128   // ceil(MAX_NODES/SCAN_B) = 98

__device__ float g_h1[(size_t)MAX_NODES * 128];     // 51.2 MB
__device__ float g_tmp[(size_t)MAX_NODES * 32];     // 12.8 MB
__device__ int   g_counts[MAX_NODES];
__device__ int   g_row_ptr[MAX_NODES];
__device__ int   g_cursor[MAX_NODES];
__device__ int   g_blk_sums[MAX_BLKS];
__device__ int   g_col_s[MAX_EDGES];                // 6.4 MB
__device__ float g_val_s[MAX_EDGES];                // 6.4 MB

// ---------------------------------------------------------------------------
// CSR build
// ---------------------------------------------------------------------------
__global__ void zero_counts_kernel(int* __restrict__ counts, int n) {
    int i = blockIdx.x * blockDim.x + threadIdx.x;
    if (i < n) counts[i] = 0;
}

__global__ void count_rows_kernel(const int* __restrict__ row,
                                  int* __restrict__ counts, int E) {
    int e = blockIdx.x * blockDim.x + threadIdx.x;
    if (e < E) atomicAdd(&counts[row[e]], 1);
}

// per-block exclusive scan (Hillis-Steele), emits block sums
__global__ __launch_bounds__(SCAN_B) void scan_block_kernel(
    const int* __restrict__ counts, int* __restrict__ excl,
    int* __restrict__ blk_sums, int n) {
    __shared__ int s[SCAN_B];
    int tid = threadIdx.x;
    int i = blockIdx.x * SCAN_B + tid;
    int v = (i < n) ? counts[i] : 0;
    s[tid] = v;
    __syncthreads();
#pragma unroll
    for (int off = 1; off < SCAN_B; off <<= 1) {
        int t = 0;
        if (tid >= off) t = s[tid - off];
        __syncthreads();
        if (tid >= off) s[tid] += t;
        __syncthreads();
    }
    if (i < n) excl[i] = s[tid] - v;          // exclusive
    if (tid == SCAN_B - 1) blk_sums[blockIdx.x] = s[tid];
}

// single-block exclusive scan of block sums (nb <= MAX_BLKS)
__global__ __launch_bounds__(MAX_BLKS) void scan_sums_kernel(
    int* __restrict__ blk_sums, int nb) {
    __shared__ int s[MAX_BLKS];
    int tid = threadIdx.x;
    int v = (tid < nb) ? blk_sums[tid] : 0;
    s[tid] = v;
    __syncthreads();
#pragma unroll
    for (int off = 1; off < MAX_BLKS; off <<= 1) {
        int t = 0;
        if (tid >= off) t = s[tid - off];
        __syncthreads();
        if (tid >= off) s[tid] += t;
        __syncthreads();
    }
    if (tid < nb) blk_sums[tid] = s[tid] - v;  // exclusive
}

__global__ void add_offsets_kernel(int* __restrict__ row_ptr,
                                   int* __restrict__ cursor,
                                   const int* __restrict__ blk_sums, int n) {
    int i = blockIdx.x * blockDim.x + threadIdx.x;
    if (i < n) {
        int p = row_ptr[i] + blk_sums[i >> 10];
        row_ptr[i] = p;
        cursor[i]  = p;
    }
}

__global__ void scatter_edges_kernel(const int* __restrict__ row,
                                     const int* __restrict__ col,
                                     const float* __restrict__ val,
                                     int* __restrict__ cursor,
                                     int* __restrict__ col_s,
                                     float* __restrict__ val_s, int E) {
    int e = blockIdx.x * blockDim.x + threadIdx.x;
    if (e < E) {
        int p = atomicAdd(&cursor[row[e]], 1);
        col_s[p] = col[e];
        val_s[p] = val[e];
    }
}

// ---------------------------------------------------------------------------
// GEMM chunk: C[N, 32] = act(A)[N, 128] @ W[128, c0:c0+32]
// BM=128, BK=32, 256 threads, 4x4 register tile (16 outputs/thread).
// Inner loop: 2 x LDS.128 per 16 FFMA (2 B/FMA).
// ---------------------------------------------------------------------------
template <bool RELU>
__global__ __launch_bounds__(256) void gemm_chunk32_kernel(
    const float* __restrict__ A, const float* __restrict__ W,
    float* __restrict__ C, int N, int WN, int c0) {
    constexpr int BM = 128, BK = 32, K = 128, LDA = 132;

    __shared__ float As[BK][LDA];     // transposed A tile, padded
    __shared__ float Ws[BK][32];

    const int tid = threadIdx.x;
    const int m0  = blockIdx.x * BM;
    const int tm  = tid >> 3;         // 0..31 -> rows tm*4..tm*4+3
    const int tn  = tid & 7;          // 0..7  -> cols tn*4..tn*4+3

    float acc[4][4];
#pragma unroll
    for (int i = 0; i < 4; ++i)
#pragma unroll
        for (int j = 0; j < 4; ++j) acc[i][j] = 0.f;

    const int ar  = tid >> 3;         // A load: rows ar + {0,32,64,96}
    const int ac4 = (tid & 7) * 4;    // cols ac4..ac4+3
    const int wk  = tid >> 3;         // W load row
    const int wc4 = (tid & 7) * 4;    // W load col

    for (int kt = 0; kt < K; kt += BK) {
#pragma unroll
        for (int i = 0; i < 4; ++i) {
            int row = m0 + ar + i * 32;
            float4 v = make_float4(0.f, 0.f, 0.f, 0.f);
            if (row < N)
                v = *reinterpret_cast<const float4*>(A + (size_t)row * K + kt + ac4);
            if (RELU) {
                v.x = fmaxf(v.x, 0.f); v.y = fmaxf(v.y, 0.f);
                v.z = fmaxf(v.z, 0.f); v.w = fmaxf(v.w, 0.f);
            }
            int r = ar + i * 32;
            As[ac4 + 0][r] = v.x;
            As[ac4 + 1][r] = v.y;
            As[ac4 + 2][r] = v.z;
            As[ac4 + 3][r] = v.w;
        }
        *reinterpret_cast<float4*>(&Ws[wk][wc4]) =
            *reinterpret_cast<const float4*>(W + (size_t)(kt + wk) * WN + c0 + wc4);
        __syncthreads();

#pragma unroll
        for (int k = 0; k < BK; ++k) {
            float4 a = *reinterpret_cast<const float4*>(&As[k][tm * 4]);
            float4 b = *reinterpret_cast<const float4*>(&Ws[k][tn * 4]);
            float av[4] = {a.x, a.y, a.z, a.w};
            float bv[4] = {b.x, b.y, b.z, b.w};
#pragma unroll
            for (int i = 0; i < 4; ++i)
#pragma unroll
                for (int j = 0; j < 4; ++j)
                    acc[i][j] = fmaf(av[i], bv[j], acc[i][j]);
        }
        __syncthreads();
    }

#pragma unroll
    for (int i = 0; i < 4; ++i) {
        int row = m0 + tm * 4 + i;
        if (row < N)
            *reinterpret_cast<float4*>(C + (size_t)row * 32 + tn * 4) =
                make_float4(acc[i][0], acc[i][1], acc[i][2], acc[i][3]);
    }
}

// ---------------------------------------------------------------------------
// CSR SpMM chunk (32 channels): one warp per row, lane = channel.
// acc starts at bias; one coalesced 128B gather per edge; single store.
// ---------------------------------------------------------------------------
__global__ __launch_bounds__(256) void spmm_csr32_kernel(
    const int* __restrict__ row_ptr, const int* __restrict__ counts,
    const int* __restrict__ col_s, const float* __restrict__ val_s,
    const float* __restrict__ x, const float* __restrict__ bias,
    float* __restrict__ out, int N, int LD, int c0) {
    int r = blockIdx.x * 8 + (threadIdx.x >> 5);
    if (r >= N) return;
    int lane = threadIdx.x & 31;

    float acc = __ldg(&bias[c0 + lane]);
    int j   = row_ptr[r];
    int end = j + counts[r];

    for (; j + 3 < end; j += 4) {
        int   c0i = col_s[j],     c1i = col_s[j + 1];
        int   c2i = col_s[j + 2], c3i = col_s[j + 3];
        float v0 = val_s[j],      v1 = val_s[j + 1];
        float v2 = val_s[j + 2],  v3 = val_s[j + 3];
        float x0 = x[(size_t)c0i * 32 + lane];
        float x1 = x[(size_t)c1i * 32 + lane];
        float x2 = x[(size_t)c2i * 32 + lane];
        float x3 = x[(size_t)c3i * 32 + lane];
        acc = fmaf(v0, x0, acc);
        acc = fmaf(v1, x1, acc);
        acc = fmaf(v2, x2, acc);
        acc = fmaf(v3, x3, acc);
    }
    for (; j < end; ++j) {
        int   c = col_s[j];
        float v = val_s[j];
        acc = fmaf(v, x[(size_t)c * 32 + lane], acc);
    }
    out[(size_t)r * LD + c0 + lane] = acc;
}

// ---------------------------------------------------------------------------
// launch
// ---------------------------------------------------------------------------
extern "C" void kernel_launch(void* const* d_in, const int* in_sizes, int n_in,
                              void* d_out, int out_size) {
    const float* x   = (const float*)d_in[0];
    const int*   row = (const int*)d_in[1];
    const int*   col = (const int*)d_in[2];
    const float* val = (const float*)d_in[3];
    const float* w1  = (const float*)d_in[4];
    const float* b1  = (const float*)d_in[5];
    const float* w2  = (const float*)d_in[6];
    const float* b2  = (const float*)d_in[7];
    float* out = (float*)d_out;

    const int N = in_sizes[0] >> 7;   // x is [N, 128]
    const int E = in_sizes[1];

    float *h1, *tmp, *val_s;
    int *counts, *row_ptr, *cursor, *blk_sums, *col_s;
    cudaGetSymbolAddress((void**)&h1, g_h1);
    cudaGetSymbolAddress((void**)&tmp, g_tmp);
    cudaGetSymbolAddress((void**)&counts, g_counts);
    cudaGetSymbolAddress((void**)&row_ptr, g_row_ptr);
    cudaGetSymbolAddress((void**)&cursor, g_cursor);
    cudaGetSymbolAddress((void**)&blk_sums, g_blk_sums);
    cudaGetSymbolAddress((void**)&col_s, g_col_s);
    cudaGetSymbolAddress((void**)&val_s, g_val_s);

    const int nblk_scan = (N + SCAN_B - 1) / SCAN_B;

    // --- CSR build ---
    zero_counts_kernel<<<(N + 255) / 256, 256>>>(counts, N);
    count_rows_kernel<<<(E + 255) / 256, 256>>>(row, counts, E);
    scan_block_kernel<<<nblk_scan, SCAN_B>>>(counts, row_ptr, blk_sums, N);
    scan_sums_kernel<<<1, MAX_BLKS>>>(blk_sums, nblk_scan);
    add_offsets_kernel<<<(N + 255) / 256, 256>>>(row_ptr, cursor, blk_sums, N);
    scatter_edges_kernel<<<(E + 255) / 256, 256>>>(row, col, val, cursor,
                                                   col_s, val_s, E);

    const int gemm_blocks = (N + 127) / 128;
    const int spmm_blocks = (N + 7) / 8;

    // --- layer 1: 4 chunks of 32 hidden channels ---
    for (int c0 = 0; c0 < 128; c0 += 32) {
        gemm_chunk32_kernel<false><<<gemm_blocks, 256>>>(x, w1, tmp, N, 128, c0);
        spmm_csr32_kernel<<<spmm_blocks, 256>>>(row_ptr, counts, col_s, val_s,
                                                tmp, b1, h1, N, 128, c0);
    }
    // --- layer 2: 2 chunks of 32 output channels ---
    for (int c0 = 0; c0 < 64; c0 += 32) {
        gemm_chunk32_kernel<true><<<gemm_blocks, 256>>>(h1, w2, tmp, N, 64, c0);
        spmm_csr32_kernel<<<spmm_blocks, 256>>>(row_ptr, counts, col_s, val_s,
                                                tmp, b2, out, N, 64, c0);
    }
}

// round 4
// speedup vs baseline: 1.4132x; 1.0376x over previous
#include <cuda_runtime.h>
#include <cuda_fp16.h>

// GCN link predictor, restructured + CSR + fp16 intermediates:
//   CSR build (per call): histogram -> scan -> bucket scatter (int2 edges)
//   y1 = x @ w1            (fp32 GEMM, fp16 output, all 128 cols, 1 launch)
//   h1 = b1 + A @ y1       (CSR warp-per-row SpMM, fp16 gather, fp32 out)
//   y2 = relu(h1) @ w2     (fp32 GEMM, fp16 output, 64 cols)
//   out = b2 + A @ y2      (CSR SpMM, fp32 out)
// Valid: relu((A@x)@w1+b1) == relu(A@(x@w1)+b1), (A@h)@w2+b2 == A@(h@w2)+b2.

#define MAX_NODES 100000
#define MAX_EDGES 1600000
#define SCAN_B    1024
#define MAX_BLKS  128   // ceil(MAX_NODES/SCAN_B) = 98

__device__ float  g_h1[(size_t)MAX_NODES * 128];      // 51.2 MB
__device__ __half g_tmp16[(size_t)MAX_NODES * 128];   // 25.6 MB
__device__ int2   g_edges[MAX_EDGES];                 // 12.8 MB (col, val bits)
__device__ int    g_counts[MAX_NODES];
__device__ int    g_row_ptr[MAX_NODES];
__device__ int    g_cursor[MAX_NODES];
__device__ int    g_blk_sums[MAX_BLKS];

// ---------------------------------------------------------------------------
// CSR build
// ---------------------------------------------------------------------------
__global__ void zero_counts_kernel(int* __restrict__ counts, int n) {
    int i = blockIdx.x * blockDim.x + threadIdx.x;
    if (i < n) counts[i] = 0;
}

__global__ void count_rows_kernel(const int* __restrict__ row,
                                  int* __restrict__ counts, int E) {
    int e = blockIdx.x * blockDim.x + threadIdx.x;
    if (e < E) atomicAdd(&counts[row[e]], 1);
}

__global__ __launch_bounds__(SCAN_B) void scan_block_kernel(
    const int* __restrict__ counts, int* __restrict__ excl,
    int* __restrict__ blk_sums, int n) {
    __shared__ int s[SCAN_B];
    int tid = threadIdx.x;
    int i = blockIdx.x * SCAN_B + tid;
    int v = (i < n) ? counts[i] : 0;
    s[tid] = v;
    __syncthreads();
#pragma unroll
    for (int off = 1; off < SCAN_B; off <<= 1) {
        int t = 0;
        if (tid >= off) t = s[tid - off];
        __syncthreads();
        if (tid >= off) s[tid] += t;
        __syncthreads();
    }
    if (i < n) excl[i] = s[tid] - v;
    if (tid == SCAN_B - 1) blk_sums[blockIdx.x] = s[tid];
}

__global__ __launch_bounds__(MAX_BLKS) void scan_sums_kernel(
    int* __restrict__ blk_sums, int nb) {
    __shared__ int s[MAX_BLKS];
    int tid = threadIdx.x;
    int v = (tid < nb) ? blk_sums[tid] : 0;
    s[tid] = v;
    __syncthreads();
#pragma unroll
    for (int off = 1; off < MAX_BLKS; off <<= 1) {
        int t = 0;
        if (tid >= off) t = s[tid - off];
        __syncthreads();
        if (tid >= off) s[tid] += t;
        __syncthreads();
    }
    if (tid < nb) blk_sums[tid] = s[tid] - v;
}

__global__ void add_offsets_kernel(int* __restrict__ row_ptr,
                                   int* __restrict__ cursor,
                                   const int* __restrict__ blk_sums, int n) {
    int i = blockIdx.x * blockDim.x + threadIdx.x;
    if (i < n) {
        int p = row_ptr[i] + blk_sums[i >> 10];
        row_ptr[i] = p;
        cursor[i]  = p;
    }
}

__global__ void scatter_edges_kernel(const int* __restrict__ row,
                                     const int* __restrict__ col,
                                     const float* __restrict__ val,
                                     int* __restrict__ cursor,
                                     int2* __restrict__ edges, int E) {
    int e = blockIdx.x * blockDim.x + threadIdx.x;
    if (e < E) {
        int p = atomicAdd(&cursor[row[e]], 1);
        edges[p] = make_int2(col[e], __float_as_int(val[e]));
    }
}

// ---------------------------------------------------------------------------
// GEMM: C16[N, c0:c0+32] = act(A)[N, 128] @ W[128, c0:c0+32], c0 = 32*blockIdx.y
// BM=128, BK=32, 256 threads, 4x4 register tile, fp32 accumulate, fp16 store.
// ---------------------------------------------------------------------------
template <bool RELU>
__global__ __launch_bounds__(256) void gemm_chunk32_f16_kernel(
    const float* __restrict__ A, const float* __restrict__ W,
    __half* __restrict__ C, int N, int WN) {
    constexpr int BM = 128, BK = 32, K = 128, LDA = 132;

    __shared__ float As[BK][LDA];
    __shared__ float Ws[BK][32];

    const int tid = threadIdx.x;
    const int m0  = blockIdx.x * BM;
    const int c0  = blockIdx.y * 32;
    const int tm  = tid >> 3;
    const int tn  = tid & 7;

    float acc[4][4];
#pragma unroll
    for (int i = 0; i < 4; ++i)
#pragma unroll
        for (int j = 0; j < 4; ++j) acc[i][j] = 0.f;

    const int ar  = tid >> 3;
    const int ac4 = (tid & 7) * 4;
    const int wk  = tid >> 3;
    const int wc4 = (tid & 7) * 4;

    for (int kt = 0; kt < K; kt += BK) {
#pragma unroll
        for (int i = 0; i < 4; ++i) {
            int row = m0 + ar + i * 32;
            float4 v = make_float4(0.f, 0.f, 0.f, 0.f);
            if (row < N)
                v = *reinterpret_cast<const float4*>(A + (size_t)row * K + kt + ac4);
            if (RELU) {
                v.x = fmaxf(v.x, 0.f); v.y = fmaxf(v.y, 0.f);
                v.z = fmaxf(v.z, 0.f); v.w = fmaxf(v.w, 0.f);
            }
            int r = ar + i * 32;
            As[ac4 + 0][r] = v.x;
            As[ac4 + 1][r] = v.y;
            As[ac4 + 2][r] = v.z;
            As[ac4 + 3][r] = v.w;
        }
        *reinterpret_cast<float4*>(&Ws[wk][wc4]) =
            *reinterpret_cast<const float4*>(W + (size_t)(kt + wk) * WN + c0 + wc4);
        __syncthreads();

#pragma unroll
        for (int k = 0; k < BK; ++k) {
            float4 a = *reinterpret_cast<const float4*>(&As[k][tm * 4]);
            float4 b = *reinterpret_cast<const float4*>(&Ws[k][tn * 4]);
            float av[4] = {a.x, a.y, a.z, a.w};
            float bv[4] = {b.x, b.y, b.z, b.w};
#pragma unroll
            for (int i = 0; i < 4; ++i)
#pragma unroll
                for (int j = 0; j < 4; ++j)
                    acc[i][j] = fmaf(av[i], bv[j], acc[i][j]);
        }
        __syncthreads();
    }

#pragma unroll
    for (int i = 0; i < 4; ++i) {
        int row = m0 + tm * 4 + i;
        if (row < N) {
            __half2 h0 = __floats2half2_rn(acc[i][0], acc[i][1]);
            __half2 h1 = __floats2half2_rn(acc[i][2], acc[i][3]);
            __half2* dst = reinterpret_cast<__half2*>(
                C + (size_t)row * WN + c0 + tn * 4);
            dst[0] = h0;
            dst[1] = h1;
        }
    }
}

// ---------------------------------------------------------------------------
// CSR SpMM, 128 channels fp16 src: one warp per row, lane handles 4 channels.
// Gather = uint2 (4 halfs) per lane -> 256B/warp coalesced. fp32 accumulate.
// ---------------------------------------------------------------------------
__global__ __launch_bounds__(256) void spmm_csr128_f16_kernel(
    const int* __restrict__ row_ptr, const int* __restrict__ counts,
    const int2* __restrict__ edges, const __half* __restrict__ y,
    const float* __restrict__ bias, float* __restrict__ out, int N) {
    int r = blockIdx.x * 8 + (threadIdx.x >> 5);
    if (r >= N) return;
    int lane = threadIdx.x & 31;

    float4 bv = *reinterpret_cast<const float4*>(bias + lane * 4);
    float acc0 = bv.x, acc1 = bv.y, acc2 = bv.z, acc3 = bv.w;

    int j   = row_ptr[r];
    int end = j + counts[r];

    for (; j + 1 < end; j += 2) {
        int2 e0 = edges[j];
        int2 e1 = edges[j + 1];
        float v0 = __int_as_float(e0.y);
        float v1 = __int_as_float(e1.y);
        uint2 g0 = *reinterpret_cast<const uint2*>(y + (size_t)e0.x * 128 + lane * 4);
        uint2 g1 = *reinterpret_cast<const uint2*>(y + (size_t)e1.x * 128 + lane * 4);
        float2 a0 = __half22float2(*reinterpret_cast<__half2*>(&g0.x));
        float2 a1 = __half22float2(*reinterpret_cast<__half2*>(&g0.y));
        acc0 = fmaf(v0, a0.x, acc0); acc1 = fmaf(v0, a0.y, acc1);
        acc2 = fmaf(v0, a1.x, acc2); acc3 = fmaf(v0, a1.y, acc3);
        float2 b0 = __half22float2(*reinterpret_cast<__half2*>(&g1.x));
        float2 b1 = __half22float2(*reinterpret_cast<__half2*>(&g1.y));
        acc0 = fmaf(v1, b0.x, acc0); acc1 = fmaf(v1, b0.y, acc1);
        acc2 = fmaf(v1, b1.x, acc2); acc3 = fmaf(v1, b1.y, acc3);
    }
    if (j < end) {
        int2 e0 = edges[j];
        float v0 = __int_as_float(e0.y);
        uint2 g0 = *reinterpret_cast<const uint2*>(y + (size_t)e0.x * 128 + lane * 4);
        float2 a0 = __half22float2(*reinterpret_cast<__half2*>(&g0.x));
        float2 a1 = __half22float2(*reinterpret_cast<__half2*>(&g0.y));
        acc0 = fmaf(v0, a0.x, acc0); acc1 = fmaf(v0, a0.y, acc1);
        acc2 = fmaf(v0, a1.x, acc2); acc3 = fmaf(v0, a1.y, acc3);
    }
    *reinterpret_cast<float4*>(out + (size_t)r * 128 + lane * 4) =
        make_float4(acc0, acc1, acc2, acc3);
}

// ---------------------------------------------------------------------------
// CSR SpMM, 64 channels fp16 src: one warp per row, lane handles 2 channels.
// ---------------------------------------------------------------------------
__global__ __launch_bounds__(256) void spmm_csr64_f16_kernel(
    const int* __restrict__ row_ptr, const int* __restrict__ counts,
    const int2* __restrict__ edges, const __half* __restrict__ y,
    const float* __restrict__ bias, float* __restrict__ out, int N) {
    int r = blockIdx.x * 8 + (threadIdx.x >> 5);
    if (r >= N) return;
    int lane = threadIdx.x & 31;

    float2 bv = *reinterpret_cast<const float2*>(bias + lane * 2);
    float acc0 = bv.x, acc1 = bv.y;

    int j   = row_ptr[r];
    int end = j + counts[r];

    for (; j + 1 < end; j += 2) {
        int2 e0 = edges[j];
        int2 e1 = edges[j + 1];
        float v0 = __int_as_float(e0.y);
        float v1 = __int_as_float(e1.y);
        __half2 g0 = *reinterpret_cast<const __half2*>(y + (size_t)e0.x * 64 + lane * 2);
        __half2 g1 = *reinterpret_cast<const __half2*>(y + (size_t)e1.x * 64 + lane * 2);
        float2 a0 = __half22float2(g0);
        float2 a1 = __half22float2(g1);
        acc0 = fmaf(v0, a0.x, acc0); acc1 = fmaf(v0, a0.y, acc1);
        acc0 = fmaf(v1, a1.x, acc0); acc1 = fmaf(v1, a1.y, acc1);
    }
    if (j < end) {
        int2 e0 = edges[j];
        float v0 = __int_as_float(e0.y);
        __half2 g0 = *reinterpret_cast<const __half2*>(y + (size_t)e0.x * 64 + lane * 2);
        float2 a0 = __half22float2(g0);
        acc0 = fmaf(v0, a0.x, acc0); acc1 = fmaf(v0, a0.y, acc1);
    }
    *reinterpret_cast<float2*>(out + (size_t)r * 64 + lane * 2) =
        make_float2(acc0, acc1);
}

// ---------------------------------------------------------------------------
// launch
// ---------------------------------------------------------------------------
extern "C" void kernel_launch(void* const* d_in, const int* in_sizes, int n_in,
                              void* d_out, int out_size) {
    const float* x   = (const float*)d_in[0];
    const int*   row = (const int*)d_in[1];
    const int*   col = (const int*)d_in[2];
    const float* val = (const float*)d_in[3];
    const float* w1  = (const float*)d_in[4];
    const float* b1  = (const float*)d_in[5];
    const float* w2  = (const float*)d_in[6];
    const float* b2  = (const float*)d_in[7];
    float* out = (float*)d_out;

    const int N = in_sizes[0] >> 7;   // x is [N, 128]
    const int E = in_sizes[1];

    float  *h1;
    __half *tmp16;
    int2   *edges;
    int *counts, *row_ptr, *cursor, *blk_sums;
    cudaGetSymbolAddress((void**)&h1, g_h1);
    cudaGetSymbolAddress((void**)&tmp16, g_tmp16);
    cudaGetSymbolAddress((void**)&edges, g_edges);
    cudaGetSymbolAddress((void**)&counts, g_counts);
    cudaGetSymbolAddress((void**)&row_ptr, g_row_ptr);
    cudaGetSymbolAddress((void**)&cursor, g_cursor);
    cudaGetSymbolAddress((void**)&blk_sums, g_blk_sums);

    const int nblk_scan = (N + SCAN_B - 1) / SCAN_B;

    // --- CSR build ---
    zero_counts_kernel<<<(N + 255) / 256, 256>>>(counts, N);
    count_rows_kernel<<<(E + 255) / 256, 256>>>(row, counts, E);
    scan_block_kernel<<<nblk_scan, SCAN_B>>>(counts, row_ptr, blk_sums, N);
    scan_sums_kernel<<<1, MAX_BLKS>>>(blk_sums, nblk_scan);
    add_offsets_kernel<<<(N + 255) / 256, 256>>>(row_ptr, cursor, blk_sums, N);
    scatter_edges_kernel<<<(E + 255) / 256, 256>>>(row, col, val, cursor,
                                                   edges, E);

    const int gemm_mblocks = (N + 127) / 128;
    const int spmm_blocks  = (N + 7) / 8;

    // --- layer 1 ---
    gemm_chunk32_f16_kernel<false><<<dim3(gemm_mblocks, 4), 256>>>(
        x, w1, tmp16, N, 128);
    spmm_csr128_f16_kernel<<<spmm_blocks, 256>>>(row_ptr, counts, edges,
                                                 tmp16, b1, h1, N);
    // --- layer 2 ---
    gemm_chunk32_f16_kernel<true><<<dim3(gemm_mblocks, 2), 256>>>(
        h1, w2, tmp16, N, 64);
    spmm_csr64_f16_kernel<<<spmm_blocks, 256>>>(row_ptr, counts, edges,
                                                tmp16, b2, out, N);
}

// round 5
// speedup vs baseline: 3.6922x; 2.6127x over previous
#include <cuda_runtime.h>
#include <cuda_fp16.h>
#include <cstdint>

// GCN link predictor: CSR + fp16 HMMA GEMMs + fp16 intermediates.
//   CSR build (per call): histogram -> scan -> bucket scatter (int2 edges)
//   y1  = x @ w1              (HMMA GEMM, fp32->fp16 A convert in-tile)
//   h16 = relu(b1 + A @ y1)   (CSR warp-per-row SpMM, fp16 out, relu fused)
//   y2  = h16 @ w2            (HMMA GEMM, fp16 A)
//   out = b2 + A @ y2         (CSR SpMM, fp32 out)
// Valid: relu((A@x)@w1+b1) == relu(A@(x@w1)+b1), (A@h)@w2+b2 == A@(h@w2)+b2.

#define MAX_NODES 100000
#define MAX_EDGES 1600000
#define SCAN_B    1024
#define MAX_BLKS  128

__device__ __half g_y16[(size_t)MAX_NODES * 128];   // 25.6 MB (y1 / y2)
__device__ __half g_h16[(size_t)MAX_NODES * 128];   // 25.6 MB (relu(h1))
__device__ int2   g_edges[MAX_EDGES];               // 12.8 MB
__device__ __half g_w1h[128 * 128];
__device__ __half g_w2h[128 * 64];
__device__ int    g_counts[MAX_NODES];
__device__ int    g_row_ptr[MAX_NODES];
__device__ int    g_cursor[MAX_NODES];
__device__ int    g_blk_sums[MAX_BLKS];

// ---------------------------------------------------------------------------
// helpers
// ---------------------------------------------------------------------------
__device__ __forceinline__ uint32_t smem_u32(const void* p) {
    uint32_t r;
    asm("{ .reg .u64 t; cvta.to.shared.u64 t, %1; cvt.u32.u64 %0, t; }"
        : "=r"(r) : "l"(p));
    return r;
}

// ---------------------------------------------------------------------------
// CSR build
// ---------------------------------------------------------------------------
__global__ void zero_counts_kernel(int* __restrict__ counts, int n) {
    int i = blockIdx.x * blockDim.x + threadIdx.x;
    if (i < n) counts[i] = 0;
}

__global__ void count_rows_kernel(const int* __restrict__ row,
                                  int* __restrict__ counts, int E) {
    int e = blockIdx.x * blockDim.x + threadIdx.x;
    if (e < E) atomicAdd(&counts[row[e]], 1);
}

__global__ __launch_bounds__(SCAN_B) void scan_block_kernel(
    const int* __restrict__ counts, int* __restrict__ excl,
    int* __restrict__ blk_sums, int n) {
    __shared__ int s[SCAN_B];
    int tid = threadIdx.x;
    int i = blockIdx.x * SCAN_B + tid;
    int v = (i < n) ? counts[i] : 0;
    s[tid] = v;
    __syncthreads();
#pragma unroll
    for (int off = 1; off < SCAN_B; off <<= 1) {
        int t = 0;
        if (tid >= off) t = s[tid - off];
        __syncthreads();
        if (tid >= off) s[tid] += t;
        __syncthreads();
    }
    if (i < n) excl[i] = s[tid] - v;
    if (tid == SCAN_B - 1) blk_sums[blockIdx.x] = s[tid];
}

__global__ __launch_bounds__(MAX_BLKS) void scan_sums_kernel(
    int* __restrict__ blk_sums, int nb) {
    __shared__ int s[MAX_BLKS];
    int tid = threadIdx.x;
    int v = (tid < nb) ? blk_sums[tid] : 0;
    s[tid] = v;
    __syncthreads();
#pragma unroll
    for (int off = 1; off < MAX_BLKS; off <<= 1) {
        int t = 0;
        if (tid >= off) t = s[tid - off];
        __syncthreads();
        if (tid >= off) s[tid] += t;
        __syncthreads();
    }
    if (tid < nb) blk_sums[tid] = s[tid] - v;
}

__global__ void add_offsets_kernel(int* __restrict__ row_ptr,
                                   int* __restrict__ cursor,
                                   const int* __restrict__ blk_sums, int n) {
    int i = blockIdx.x * blockDim.x + threadIdx.x;
    if (i < n) {
        int p = row_ptr[i] + blk_sums[i >> 10];
        row_ptr[i] = p;
        cursor[i]  = p;
    }
}

__global__ void scatter_edges_kernel(const int* __restrict__ row,
                                     const int* __restrict__ col,
                                     const float* __restrict__ val,
                                     int* __restrict__ cursor,
                                     int2* __restrict__ edges, int E) {
    int e = blockIdx.x * blockDim.x + threadIdx.x;
    if (e < E) {
        int p = atomicAdd(&cursor[row[e]], 1);
        edges[p] = make_int2(col[e], __float_as_int(val[e]));
    }
}

// ---------------------------------------------------------------------------
// weight fp32 -> fp16 convert (both weights, one launch)
// ---------------------------------------------------------------------------
__global__ void convert_w_kernel(const float* __restrict__ w1,
                                 const float* __restrict__ w2,
                                 __half* __restrict__ w1h,
                                 __half* __restrict__ w2h) {
    int i = blockIdx.x * blockDim.x + threadIdx.x;
    if (i < 128 * 128) w1h[i] = __float2half_rn(w1[i]);
    if (i < 128 * 64)  w2h[i] = __float2half_rn(w2[i]);
}

// ---------------------------------------------------------------------------
// HMMA GEMM: C16[N, c0:c0+64] = A[N, 128] @ W16[128, c0:c0+64], c0=64*blockIdx.y
// BM=128, BN=64, BK=128 (whole K). 256 threads = 8 warps (4 m x 2 n).
// Each warp: 32x32 via 2x4 m16n8k16 frags. XOR-swizzled smem (48KB),
// conflict-free ldmatrix. A fp32 (converted in-tile) or fp16.
// ---------------------------------------------------------------------------
template <bool A_FP32>
__global__ __launch_bounds__(256) void gemm_mma_kernel(
    const void* __restrict__ Ap, const __half* __restrict__ W,
    __half* __restrict__ C, int N, int WN) {
    extern __shared__ char smem[];
    // As: [128][128] half, row stride 256B, chunk(16B) swizzle p = ch ^ (row&7)
    // Bs: [128][64]  half, row stride 128B, same swizzle, base +32768
    const int tid = threadIdx.x;
    const int m0  = blockIdx.x * 128;
    const int c0  = blockIdx.y * 64;

    // --- load A tile (128 x 128 halfs) ---
#pragma unroll
    for (int i = 0; i < 8; ++i) {
        int cid = tid + i * 256;        // 0..2047
        int row = cid >> 4;
        int ch  = cid & 15;
        int p   = ch ^ (row & 7);
        int rg  = m0 + row;
        uint4 o = make_uint4(0u, 0u, 0u, 0u);
        if (A_FP32) {
            if (rg < N) {
                const float4* src = reinterpret_cast<const float4*>(
                    (const float*)Ap + (size_t)rg * 128 + ch * 8);
                float4 v0 = src[0], v1 = src[1];
                __half2 h0 = __floats2half2_rn(v0.x, v0.y);
                __half2 h1 = __floats2half2_rn(v0.z, v0.w);
                __half2 h2 = __floats2half2_rn(v1.x, v1.y);
                __half2 h3 = __floats2half2_rn(v1.z, v1.w);
                o.x = *reinterpret_cast<uint32_t*>(&h0);
                o.y = *reinterpret_cast<uint32_t*>(&h1);
                o.z = *reinterpret_cast<uint32_t*>(&h2);
                o.w = *reinterpret_cast<uint32_t*>(&h3);
            }
        } else {
            if (rg < N)
                o = *reinterpret_cast<const uint4*>(
                    (const __half*)Ap + (size_t)rg * 128 + ch * 8);
        }
        *reinterpret_cast<uint4*>(smem + row * 256 + p * 16) = o;
    }
    // --- load B tile (128 x 64 halfs) ---
#pragma unroll
    for (int i = 0; i < 4; ++i) {
        int cid = tid + i * 256;        // 0..1023
        int k  = cid >> 3;
        int ch = cid & 7;
        int p  = ch ^ (k & 7);
        uint4 v = *reinterpret_cast<const uint4*>(W + (size_t)k * WN + c0 + ch * 8);
        *reinterpret_cast<uint4*>(smem + 32768 + k * 128 + p * 16) = v;
    }
    __syncthreads();

    const int wid  = tid >> 5;
    const int lane = tid & 31;
    const int wm   = wid & 3;           // 0..3 (32 rows each)
    const int wn   = wid >> 2;          // 0..1 (32 cols each)

    float acc[2][4][4];
#pragma unroll
    for (int mf = 0; mf < 2; ++mf)
#pragma unroll
        for (int nf = 0; nf < 4; ++nf)
#pragma unroll
            for (int q = 0; q < 4; ++q) acc[mf][nf][q] = 0.f;

#pragma unroll
    for (int kf = 0; kf < 8; ++kf) {
        uint32_t a[2][4];
#pragma unroll
        for (int mf = 0; mf < 2; ++mf) {
            int row = wm * 32 + mf * 16 + (lane & 15);
            int ch  = kf * 2 + (lane >> 4);
            int p   = ch ^ (row & 7);
            uint32_t addr = smem_u32(smem + row * 256 + p * 16);
            asm volatile(
                "ldmatrix.sync.aligned.m8n8.x4.shared.b16 {%0,%1,%2,%3}, [%4];"
                : "=r"(a[mf][0]), "=r"(a[mf][1]), "=r"(a[mf][2]), "=r"(a[mf][3])
                : "r"(addr));
        }
        uint32_t b[4][2];
#pragma unroll
        for (int nf = 0; nf < 4; ++nf) {
            int k  = kf * 16 + (lane & 15);
            int ch = wn * 4 + nf;
            int p  = ch ^ (k & 7);
            uint32_t addr = smem_u32(smem + 32768 + k * 128 + p * 16);
            asm volatile(
                "ldmatrix.sync.aligned.m8n8.x2.trans.shared.b16 {%0,%1}, [%2];"
                : "=r"(b[nf][0]), "=r"(b[nf][1])
                : "r"(addr));
        }
#pragma unroll
        for (int mf = 0; mf < 2; ++mf)
#pragma unroll
            for (int nf = 0; nf < 4; ++nf) {
                asm volatile(
                    "mma.sync.aligned.m16n8k16.row.col.f32.f16.f16.f32 "
                    "{%0,%1,%2,%3}, {%4,%5,%6,%7}, {%8,%9}, {%0,%1,%2,%3};"
                    : "+f"(acc[mf][nf][0]), "+f"(acc[mf][nf][1]),
                      "+f"(acc[mf][nf][2]), "+f"(acc[mf][nf][3])
                    : "r"(a[mf][0]), "r"(a[mf][1]), "r"(a[mf][2]), "r"(a[mf][3]),
                      "r"(b[nf][0]), "r"(b[nf][1]));
            }
    }

    // --- store C (fp16) ---
#pragma unroll
    for (int mf = 0; mf < 2; ++mf)
#pragma unroll
        for (int nf = 0; nf < 4; ++nf) {
            int rg0 = m0 + wm * 32 + mf * 16 + (lane >> 2);
            int cg  = c0 + wn * 32 + nf * 8 + (lane & 3) * 2;
            if (rg0 < N)
                *reinterpret_cast<__half2*>(C + (size_t)rg0 * WN + cg) =
                    __floats2half2_rn(acc[mf][nf][0], acc[mf][nf][1]);
            int rg1 = rg0 + 8;
            if (rg1 < N)
                *reinterpret_cast<__half2*>(C + (size_t)rg1 * WN + cg) =
                    __floats2half2_rn(acc[mf][nf][2], acc[mf][nf][3]);
        }
}

// ---------------------------------------------------------------------------
// CSR SpMM, 128 ch fp16 src -> fp16 out with fused bias + relu.
// One warp per row, lane handles 4 channels. fp32 accumulate.
// ---------------------------------------------------------------------------
__global__ __launch_bounds__(256) void spmm_csr128_f16_relu_kernel(
    const int* __restrict__ row_ptr, const int* __restrict__ counts,
    const int2* __restrict__ edges, const __half* __restrict__ y,
    const float* __restrict__ bias, __half* __restrict__ out, int N) {
    int r = blockIdx.x * 8 + (threadIdx.x >> 5);
    if (r >= N) return;
    int lane = threadIdx.x & 31;

    float4 bv = *reinterpret_cast<const float4*>(bias + lane * 4);
    float acc0 = bv.x, acc1 = bv.y, acc2 = bv.z, acc3 = bv.w;

    int j   = row_ptr[r];
    int end = j + counts[r];

    for (; j + 1 < end; j += 2) {
        int2 e0 = edges[j];
        int2 e1 = edges[j + 1];
        float v0 = __int_as_float(e0.y);
        float v1 = __int_as_float(e1.y);
        uint2 g0 = *reinterpret_cast<const uint2*>(y + (size_t)e0.x * 128 + lane * 4);
        uint2 g1 = *reinterpret_cast<const uint2*>(y + (size_t)e1.x * 128 + lane * 4);
        float2 a0 = __half22float2(*reinterpret_cast<__half2*>(&g0.x));
        float2 a1 = __half22float2(*reinterpret_cast<__half2*>(&g0.y));
        acc0 = fmaf(v0, a0.x, acc0); acc1 = fmaf(v0, a0.y, acc1);
        acc2 = fmaf(v0, a1.x, acc2); acc3 = fmaf(v0, a1.y, acc3);
        float2 b0 = __half22float2(*reinterpret_cast<__half2*>(&g1.x));
        float2 b1 = __half22float2(*reinterpret_cast<__half2*>(&g1.y));
        acc0 = fmaf(v1, b0.x, acc0); acc1 = fmaf(v1, b0.y, acc1);
        acc2 = fmaf(v1, b1.x, acc2); acc3 = fmaf(v1, b1.y, acc3);
    }
    if (j < end) {
        int2 e0 = edges[j];
        float v0 = __int_as_float(e0.y);
        uint2 g0 = *reinterpret_cast<const uint2*>(y + (size_t)e0.x * 128 + lane * 4);
        float2 a0 = __half22float2(*reinterpret_cast<__half2*>(&g0.x));
        float2 a1 = __half22float2(*reinterpret_cast<__half2*>(&g0.y));
        acc0 = fmaf(v0, a0.x, acc0); acc1 = fmaf(v0, a0.y, acc1);
        acc2 = fmaf(v0, a1.x, acc2); acc3 = fmaf(v0, a1.y, acc3);
    }
    // relu + fp16 store
    __half2 h0 = __floats2half2_rn(fmaxf(acc0, 0.f), fmaxf(acc1, 0.f));
    __half2 h1 = __floats2half2_rn(fmaxf(acc2, 0.f), fmaxf(acc3, 0.f));
    uint2 o;
    o.x = *reinterpret_cast<uint32_t*>(&h0);
    o.y = *reinterpret_cast<uint32_t*>(&h1);
    *reinterpret_cast<uint2*>(out + (size_t)r * 128 + lane * 4) = o;
}

// ---------------------------------------------------------------------------
// CSR SpMM, 64 ch fp16 src -> fp32 out with fused bias (final layer).
// ---------------------------------------------------------------------------
__global__ __launch_bounds__(256) void spmm_csr64_f16_kernel(
    const int* __restrict__ row_ptr, const int* __restrict__ counts,
    const int2* __restrict__ edges, const __half* __restrict__ y,
    const float* __restrict__ bias, float* __restrict__ out, int N) {
    int r = blockIdx.x * 8 + (threadIdx.x >> 5);
    if (r >= N) return;
    int lane = threadIdx.x & 31;

    float2 bv = *reinterpret_cast<const float2*>(bias + lane * 2);
    float acc0 = bv.x, acc1 = bv.y;

    int j   = row_ptr[r];
    int end = j + counts[r];

    for (; j + 1 < end; j += 2) {
        int2 e0 = edges[j];
        int2 e1 = edges[j + 1];
        float v0 = __int_as_float(e0.y);
        float v1 = __int_as_float(e1.y);
        __half2 g0 = *reinterpret_cast<const __half2*>(y + (size_t)e0.x * 64 + lane * 2);
        __half2 g1 = *reinterpret_cast<const __half2*>(y + (size_t)e1.x * 64 + lane * 2);
        float2 a0 = __half22float2(g0);
        float2 a1 = __half22float2(g1);
        acc0 = fmaf(v0, a0.x, acc0); acc1 = fmaf(v0, a0.y, acc1);
        acc0 = fmaf(v1, a1.x, acc0); acc1 = fmaf(v1, a1.y, acc1);
    }
    if (j < end) {
        int2 e0 = edges[j];
        float v0 = __int_as_float(e0.y);
        __half2 g0 = *reinterpret_cast<const __half2*>(y + (size_t)e0.x * 64 + lane * 2);
        float2 a0 = __half22float2(g0);
        acc0 = fmaf(v0, a0.x, acc0); acc1 = fmaf(v0, a0.y, acc1);
    }
    *reinterpret_cast<float2*>(out + (size_t)r * 64 + lane * 2) =
        make_float2(acc0, acc1);
}

// ---------------------------------------------------------------------------
// launch
// ---------------------------------------------------------------------------
extern "C" void kernel_launch(void* const* d_in, const int* in_sizes, int n_in,
                              void* d_out, int out_size) {
    const float* x   = (const float*)d_in[0];
    const int*   row = (const int*)d_in[1];
    const int*   col = (const int*)d_in[2];
    const float* val = (const float*)d_in[3];
    const float* w1  = (const float*)d_in[4];
    const float* b1  = (const float*)d_in[5];
    const float* w2  = (const float*)d_in[6];
    const float* b2  = (const float*)d_in[7];
    float* out = (float*)d_out;

    const int N = in_sizes[0] >> 7;
    const int E = in_sizes[1];

    __half *y16, *h16, *w1h, *w2h;
    int2 *edges;
    int *counts, *row_ptr, *cursor, *blk_sums;
    cudaGetSymbolAddress((void**)&y16, g_y16);
    cudaGetSymbolAddress((void**)&h16, g_h16);
    cudaGetSymbolAddress((void**)&w1h, g_w1h);
    cudaGetSymbolAddress((void**)&w2h, g_w2h);
    cudaGetSymbolAddress((void**)&edges, g_edges);
    cudaGetSymbolAddress((void**)&counts, g_counts);
    cudaGetSymbolAddress((void**)&row_ptr, g_row_ptr);
    cudaGetSymbolAddress((void**)&cursor, g_cursor);
    cudaGetSymbolAddress((void**)&blk_sums, g_blk_sums);

    static bool attr_set = false;
    if (!attr_set) {
        cudaFuncSetAttribute(gemm_mma_kernel<true>,
                             cudaFuncAttributeMaxDynamicSharedMemorySize, 49152);
        cudaFuncSetAttribute(gemm_mma_kernel<false>,
                             cudaFuncAttributeMaxDynamicSharedMemorySize, 49152);
        attr_set = true;
    }

    const int nblk_scan = (N + SCAN_B - 1) / SCAN_B;

    // --- CSR build + weight convert ---
    zero_counts_kernel<<<(N + 255) / 256, 256>>>(counts, N);
    count_rows_kernel<<<(E + 255) / 256, 256>>>(row, counts, E);
    convert_w_kernel<<<64, 256>>>(w1, w2, w1h, w2h);
    scan_block_kernel<<<nblk_scan, SCAN_B>>>(counts, row_ptr, blk_sums, N);
    scan_sums_kernel<<<1, MAX_BLKS>>>(blk_sums, nblk_scan);
    add_offsets_kernel<<<(N + 255) / 256, 256>>>(row_ptr, cursor, blk_sums, N);
    scatter_edges_kernel<<<(E + 255) / 256, 256>>>(row, col, val, cursor,
                                                   edges, E);

    const int gemm_mblocks = (N + 127) / 128;
    const int spmm_blocks  = (N + 7) / 8;

    // --- layer 1: y1 = x @ w1 (fp32 A), h16 = relu(b1 + A@y1) ---
    gemm_mma_kernel<true><<<dim3(gemm_mblocks, 2), 256, 49152>>>(
        x, w1h, y16, N, 128);
    spmm_csr128_f16_relu_kernel<<<spmm_blocks, 256>>>(row_ptr, counts, edges,
                                                      y16, b1, h16, N);
    // --- layer 2: y2 = h16 @ w2 (fp16 A), out = b2 + A@y2 ---
    gemm_mma_kernel<false><<<dim3(gemm_mblocks, 1), 256, 49152>>>(
        h16, w2h, y16, N, 64);
    spmm_csr64_f16_kernel<<<spmm_blocks, 256>>>(row_ptr, counts, edges,
                                                y16, b2, out, N);
}